// round 2
// baseline (speedup 1.0000x reference)
#include <cuda_runtime.h>
#include <cuda_bf16.h>
#include <math.h>
#include <stdint.h>

#define NMAX      500000
#define DIM       128
#define SNEG      256
#define STRIDE    136          // padded bf16 row stride (conflict-free fragment loads)
#define MTILE     128
#define INV_T     10.0f
#define LOG_S     5.545177444479562f   // log(256)
#define MAXBLOCKS 4096

// Scratch: normalized embeddings in bf16 (128 MB) + per-block partial sums.
__device__ __nv_bfloat16 g_Qn[(size_t)NMAX * DIM];
__device__ float g_partial[MAXBLOCKS];
__device__ int   g_idx_is64;   // 1 if index buffers are int64, 0 if int32

// ---------------------------------------------------------------------------
// Kernel 0: detect index dtype. Reads first 1KB of the negatives buffer
// (valid for either dtype: 256*int32 = 1KB, 128*int64 = 1KB). If every int64
// interpretation lands in [0, n) the buffer is int64; otherwise int32
// (an int32 pair misreads as lo + hi*2^32, which is >= n unless hi==0).
// ---------------------------------------------------------------------------
__global__ void detect_idx_kernel(const void* __restrict__ neg, int n) {
    const long long* p = (const long long*)neg;
    long long v = p[threadIdx.x];              // 128 threads
    int ok = (v >= 0 && v < (long long)n);
    int all = __syncthreads_and(ok);
    if (threadIdx.x == 0) g_idx_is64 = all;
}

__device__ __forceinline__ long long load_index(const void* p, long long i, int is64) {
    return is64 ? ((const long long*)p)[i] : (long long)((const int*)p)[i];
}

// ---------------------------------------------------------------------------
// Kernel 1: L2-normalize each row of E into bf16. One warp per row.
// ---------------------------------------------------------------------------
__global__ void normalize_kernel(const float* __restrict__ E, int n) {
    int row  = (int)((blockIdx.x * (long long)blockDim.x + threadIdx.x) >> 5);
    int lane = threadIdx.x & 31;
    if (row >= n) return;
    float4 v = reinterpret_cast<const float4*>(E + (size_t)row * DIM)[lane];
    float ss = v.x * v.x + v.y * v.y + v.z * v.z + v.w * v.w;
#pragma unroll
    for (int o = 16; o > 0; o >>= 1) ss += __shfl_xor_sync(0xffffffffu, ss, o);
    float inv = 1.0f / fmaxf(sqrtf(ss), 1e-12f);
    __nv_bfloat162 p0 = __floats2bfloat162_rn(v.x * inv, v.y * inv);
    __nv_bfloat162 p1 = __floats2bfloat162_rn(v.z * inv, v.w * inv);
    uint2 st;
    st.x = reinterpret_cast<unsigned&>(p0);
    st.y = reinterpret_cast<unsigned&>(p1);
    reinterpret_cast<uint2*>(g_Qn + (size_t)row * DIM)[lane] = st;
}

// ---------------------------------------------------------------------------
// Kernel 2: per 128-row tile — positive dots + bf16 MMA vs all 256 negatives,
// fused exp-sum (no max subtraction needed: |logit| <= 10), per-block partial.
// ---------------------------------------------------------------------------
__global__ __launch_bounds__(256) void main_kernel(
    const void* __restrict__ pos_idx,
    const void* __restrict__ neg_idx,
    int n)
{
    extern __shared__ char smem_raw[];
    __nv_bfloat16* sQ = reinterpret_cast<__nv_bfloat16*>(smem_raw);
    __nv_bfloat16* sV = sQ + MTILE * STRIDE;
    float* sPos = reinterpret_cast<float*>(sV + SNEG * STRIDE);
    float* sRed = sPos + MTILE;

    const int tid  = threadIdx.x;
    const int lane = tid & 31;
    const int warp = tid >> 5;
    const long long tile0 = (long long)blockIdx.x * MTILE;
    const int is64 = g_idx_is64;

    // --- stage Q tile (2 threads per row, 128B halves, zero-pad tail rows) ---
    {
        int r = tid >> 1, h = tid & 1;
        long long gr = tile0 + r;
        uint4* dst = reinterpret_cast<uint4*>(sQ + r * STRIDE + h * 64);
        if (gr < n) {
            const uint4* src = reinterpret_cast<const uint4*>(
                g_Qn + (size_t)gr * DIM + h * 64);
#pragma unroll
            for (int j = 0; j < 8; j++) dst[j] = src[j];
        } else {
            uint4 z = make_uint4(0u, 0u, 0u, 0u);
#pragma unroll
            for (int j = 0; j < 8; j++) dst[j] = z;
        }
    }

    // --- stage all 256 normalized negatives (gather) ---
#pragma unroll
    for (int pass = 0; pass < 2; pass++) {
        int s = pass * 128 + (tid >> 1);
        int h = tid & 1;
        long long vr = load_index(neg_idx, s, is64);
        const uint4* src = reinterpret_cast<const uint4*>(
            g_Qn + (size_t)vr * DIM + h * 64);
        uint4* dst = reinterpret_cast<uint4*>(sV + s * STRIDE + h * 64);
#pragma unroll
        for (int j = 0; j < 8; j++) dst[j] = src[j];
    }
    __syncthreads();

    // --- positive logits: warp handles 16 rows; one gathered row dot each ---
    {
        int rb = warp * 16;
        for (int rr = rb; rr < rb + 16; rr++) {
            long long gi = tile0 + rr;
            float dot = 0.0f;
            if (gi < n) {                         // uniform per warp
                long long p = load_index(pos_idx, gi, is64);
                const __nv_bfloat162* pg = reinterpret_cast<const __nv_bfloat162*>(
                    g_Qn + (size_t)p * DIM + lane * 4);
                const __nv_bfloat162* qs = reinterpret_cast<const __nv_bfloat162*>(
                    sQ + rr * STRIDE + lane * 4);
                float2 a0 = __bfloat1622float2(pg[0]);
                float2 a1 = __bfloat1622float2(pg[1]);
                float2 b0 = __bfloat1622float2(qs[0]);
                float2 b1 = __bfloat1622float2(qs[1]);
                dot = a0.x * b0.x + a0.y * b0.y + a1.x * b1.x + a1.y * b1.y;
            }
#pragma unroll
            for (int o = 16; o > 0; o >>= 1)
                dot += __shfl_xor_sync(0xffffffffu, dot, o);
            if (lane == 0) sPos[rr] = dot * INV_T;
        }
    }
    __syncthreads();

    // --- GEMM: warp = 16 rows x 256 negs, processed in 4 chunks of 64 negs ---
    const int g  = lane >> 2;     // group id 0..7
    const int t4 = lane & 3;      // thread-in-group 0..3
    const int rbase = warp * 16;
    float rs_lo = 0.0f, rs_hi = 0.0f;

    const __nv_bfloat16* qlo = sQ + (rbase + g) * STRIDE + 2 * t4;
    const __nv_bfloat16* qhi = sQ + (rbase + g + 8) * STRIDE + 2 * t4;
    const __nv_bfloat16* vb  = sV + g * STRIDE + 2 * t4;

#pragma unroll
    for (int c = 0; c < 4; c++) {
        float acc[8][4];
#pragma unroll
        for (int i = 0; i < 8; i++) {
            acc[i][0] = 0.f; acc[i][1] = 0.f; acc[i][2] = 0.f; acc[i][3] = 0.f;
        }
#pragma unroll
        for (int k0 = 0; k0 < 8; k0++) {
            int k = k0 * 16;
            unsigned a0 = *reinterpret_cast<const unsigned*>(qlo + k);
            unsigned a1 = *reinterpret_cast<const unsigned*>(qhi + k);
            unsigned a2 = *reinterpret_cast<const unsigned*>(qlo + k + 8);
            unsigned a3 = *reinterpret_cast<const unsigned*>(qhi + k + 8);
#pragma unroll
            for (int nt = 0; nt < 8; nt++) {
                const __nv_bfloat16* vp = vb + (c * 64 + nt * 8) * STRIDE + k;
                unsigned b0 = *reinterpret_cast<const unsigned*>(vp);
                unsigned b1 = *reinterpret_cast<const unsigned*>(vp + 8);
                asm volatile(
                    "mma.sync.aligned.m16n8k16.row.col.f32.bf16.bf16.f32 "
                    "{%0,%1,%2,%3}, {%4,%5,%6,%7}, {%8,%9}, {%0,%1,%2,%3};\n"
                    : "+f"(acc[nt][0]), "+f"(acc[nt][1]),
                      "+f"(acc[nt][2]), "+f"(acc[nt][3])
                    : "r"(a0), "r"(a1), "r"(a2), "r"(a3), "r"(b0), "r"(b1));
            }
        }
        // exp-accumulate this 64-neg chunk (|logit| <= 10, fp32 safe)
#pragma unroll
        for (int nt = 0; nt < 8; nt++) {
            rs_lo += __expf(acc[nt][0] * INV_T) + __expf(acc[nt][1] * INV_T);
            rs_hi += __expf(acc[nt][2] * INV_T) + __expf(acc[nt][3] * INV_T);
        }
    }

    // reduce exp-sums across the 4 lanes of each row group
    rs_lo += __shfl_xor_sync(0xffffffffu, rs_lo, 1);
    rs_lo += __shfl_xor_sync(0xffffffffu, rs_lo, 2);
    rs_hi += __shfl_xor_sync(0xffffffffu, rs_hi, 1);
    rs_hi += __shfl_xor_sync(0xffffffffu, rs_hi, 2);

    float contrib = 0.0f;
    if (t4 == 0) {
        long long gi = tile0 + rbase + g;
        if (gi < n) contrib += sPos[rbase + g]     - (logf(rs_lo) - LOG_S);
        gi = tile0 + rbase + g + 8;
        if (gi < n) contrib += sPos[rbase + g + 8] - (logf(rs_hi) - LOG_S);
    }
#pragma unroll
    for (int o = 16; o > 0; o >>= 1)
        contrib += __shfl_xor_sync(0xffffffffu, contrib, o);
    if (lane == 0) sRed[warp] = contrib;
    __syncthreads();
    if (tid == 0) {
        float s = 0.0f;
#pragma unroll
        for (int w = 0; w < 8; w++) s += sRed[w];
        g_partial[blockIdx.x] = s;
    }
}

// ---------------------------------------------------------------------------
// Kernel 3: deterministic final reduction, loss = -sum / N
// ---------------------------------------------------------------------------
__global__ void finalize_kernel(float* __restrict__ out, int n, int nblocks) {
    __shared__ float sh[256];
    float s = 0.0f;
    for (int i = threadIdx.x; i < nblocks; i += 256) s += g_partial[i];
    sh[threadIdx.x] = s;
    __syncthreads();
    for (int o = 128; o > 0; o >>= 1) {
        if (threadIdx.x < o) sh[threadIdx.x] += sh[threadIdx.x + o];
        __syncthreads();
    }
    if (threadIdx.x == 0) out[0] = -sh[0] / (float)n;
}

// ---------------------------------------------------------------------------
extern "C" void kernel_launch(void* const* d_in, const int* in_sizes, int n_in,
                              void* d_out, int out_size) {
    const float* E   = (const float*)d_in[0];
    const void*  pos = d_in[1];
    const void*  neg = d_in[2];
    int n = in_sizes[1];   // number of edges

    // 0) detect index dtype (int32 vs int64)
    detect_idx_kernel<<<1, 128>>>(neg, n);

    // 1) normalize rows -> bf16
    int nblk_norm = (n + 7) / 8;   // 8 warps per 256-thread block, 1 row/warp
    normalize_kernel<<<nblk_norm, 256>>>(E, n);

    // 2) fused positive-dot + negative-GEMM + logsumexp
    int nblocks = (n + MTILE - 1) / MTILE;
    size_t smem = (size_t)(MTILE * STRIDE + SNEG * STRIDE) * sizeof(__nv_bfloat16)
                + (size_t)(MTILE + 8) * sizeof(float);
    cudaFuncSetAttribute(main_kernel,
                         cudaFuncAttributeMaxDynamicSharedMemorySize, (int)smem);
    main_kernel<<<nblocks, 256, smem>>>(pos, neg, n);

    // 3) deterministic reduction into the scalar output
    finalize_kernel<<<1, 256>>>((float*)d_out, n, nblocks);
}

// round 3
// speedup vs baseline: 1.2632x; 1.2632x over previous
#include <cuda_runtime.h>
#include <cuda_bf16.h>
#include <math.h>
#include <stdint.h>

#define NMAX      500000
#define DIM       128
#define SNEG      256
#define STRIDE    136          // padded bf16 row stride (conflict-free fragment loads)
#define MTILE     256          // rows per block
#define INV_T     10.0f
#define LOG_S     5.545177444479562f   // log(256)
#define MAXBLOCKS 4096

// Scratch: normalized embeddings in bf16 (128 MB) + per-block partial sums.
__device__ __nv_bfloat16 g_Qn[(size_t)NMAX * DIM];
__device__ float g_partial[MAXBLOCKS];
__device__ int   g_idx_is64;   // 1 if index buffers are int64, 0 if int32

// ---------------------------------------------------------------------------
// Kernel 0: detect index dtype (int32 vs int64) from first 1KB of negatives.
// ---------------------------------------------------------------------------
__global__ void detect_idx_kernel(const void* __restrict__ neg, int n) {
    const long long* p = (const long long*)neg;
    long long v = p[threadIdx.x];              // 128 threads -> 1KB
    int ok = (v >= 0 && v < (long long)n);
    int all = __syncthreads_and(ok);
    if (threadIdx.x == 0) g_idx_is64 = all;
}

__device__ __forceinline__ long long load_index(const void* p, long long i, int is64) {
    return is64 ? ((const long long*)p)[i] : (long long)((const int*)p)[i];
}

// ---------------------------------------------------------------------------
// Kernel 1: L2-normalize each row of E into bf16. One warp per row.
// ---------------------------------------------------------------------------
__global__ void normalize_kernel(const float* __restrict__ E, int n) {
    int row  = (int)((blockIdx.x * (long long)blockDim.x + threadIdx.x) >> 5);
    int lane = threadIdx.x & 31;
    if (row >= n) return;
    float4 v = reinterpret_cast<const float4*>(E + (size_t)row * DIM)[lane];
    float ss = v.x * v.x + v.y * v.y + v.z * v.z + v.w * v.w;
#pragma unroll
    for (int o = 16; o > 0; o >>= 1) ss += __shfl_xor_sync(0xffffffffu, ss, o);
    float inv = 1.0f / fmaxf(sqrtf(ss), 1e-12f);
    __nv_bfloat162 p0 = __floats2bfloat162_rn(v.x * inv, v.y * inv);
    __nv_bfloat162 p1 = __floats2bfloat162_rn(v.z * inv, v.w * inv);
    uint2 st;
    st.x = reinterpret_cast<unsigned&>(p0);
    st.y = reinterpret_cast<unsigned&>(p1);
    reinterpret_cast<uint2*>(g_Qn + (size_t)row * DIM)[lane] = st;
}

__device__ __forceinline__ float pairdot(unsigned a, unsigned b) {
    float2 fa = __bfloat1622float2(*reinterpret_cast<__nv_bfloat162*>(&a));
    float2 fb = __bfloat1622float2(*reinterpret_cast<__nv_bfloat162*>(&b));
    return fa.x * fb.x + fa.y * fb.y;
}

// ---------------------------------------------------------------------------
// Kernel 2: 256 rows/block. Negatives staged once in smem; A fragments come
// straight from gmem (L1-cached across the 4 chunk reloads). Warp = 32 rows.
// ---------------------------------------------------------------------------
__global__ __launch_bounds__(256, 2) void main_kernel(
    const void* __restrict__ pos_idx,
    const void* __restrict__ neg_idx,
    int n)
{
    extern __shared__ char smem_raw[];
    __nv_bfloat16* sV = reinterpret_cast<__nv_bfloat16*>(smem_raw);
    float* sPos = reinterpret_cast<float*>(sV + SNEG * STRIDE);
    float* sRed = sPos + MTILE;

    const int tid  = threadIdx.x;
    const int lane = tid & 31;
    const int warp = tid >> 5;
    const long long tile0 = (long long)blockIdx.x * MTILE;
    const int is64 = g_idx_is64;

    // --- stage all 256 normalized negatives into padded smem (1 thread/row) --
    {
        long long vr = load_index(neg_idx, tid, is64);
        const uint4* src = reinterpret_cast<const uint4*>(g_Qn + (size_t)vr * DIM);
        uint4* dst = reinterpret_cast<uint4*>(sV + tid * STRIDE);
#pragma unroll
        for (int j = 0; j < 16; j++) dst[j] = src[j];
    }

    // --- positive logits: one thread per row, straight-line fp32 dot ---------
    {
        long long row = tile0 + tid;
        float dot = 0.0f;
        if (row < n) {
            long long p = load_index(pos_idx, row, is64);
            const uint4* qa = reinterpret_cast<const uint4*>(g_Qn + (size_t)row * DIM);
            const uint4* qb = reinterpret_cast<const uint4*>(g_Qn + (size_t)p * DIM);
#pragma unroll
            for (int j = 0; j < 16; j++) {
                uint4 a = qa[j], b = qb[j];
                dot += pairdot(a.x, b.x) + pairdot(a.y, b.y)
                     + pairdot(a.z, b.z) + pairdot(a.w, b.w);
            }
        }
        sPos[tid] = dot * INV_T;
    }
    __syncthreads();

    // --- GEMM: warp = 32 rows x 256 negs, 4 chunks of 64 negs ----------------
    const int g  = lane >> 2;     // 0..7
    const int t4 = lane & 3;      // 0..3
    const long long rowG = tile0 + warp * 32 + g;   // tile 0, low half

    float rs[2][2] = {{0.f, 0.f}, {0.f, 0.f}};      // [Ttile][half]

#pragma unroll
    for (int c = 0; c < 4; c++) {
        float acc[2][8][4];
#pragma unroll
        for (int T = 0; T < 2; T++)
#pragma unroll
            for (int i = 0; i < 8; i++) {
                acc[T][i][0] = 0.f; acc[T][i][1] = 0.f;
                acc[T][i][2] = 0.f; acc[T][i][3] = 0.f;
            }

#pragma unroll
        for (int k0 = 0; k0 < 8; k0++) {
            const int k = k0 * 16 + 2 * t4;
            unsigned afr[2][4];
#pragma unroll
            for (int T = 0; T < 2; T++) {
                long long r0 = rowG + T * 16;
                long long r1 = r0 + 8;
                bool v0 = r0 < n, v1 = r1 < n;
                const unsigned* p0 = reinterpret_cast<const unsigned*>(
                    g_Qn + (size_t)r0 * DIM + k);
                const unsigned* p1 = reinterpret_cast<const unsigned*>(
                    g_Qn + (size_t)r1 * DIM + k);
                afr[T][0] = v0 ? p0[0] : 0u;
                afr[T][1] = v1 ? p1[0] : 0u;
                afr[T][2] = v0 ? p0[4] : 0u;     // +8 elements
                afr[T][3] = v1 ? p1[4] : 0u;
            }
#pragma unroll
            for (int nt = 0; nt < 8; nt++) {
                const __nv_bfloat16* vp = sV + (c * 64 + nt * 8 + g) * STRIDE
                                        + 2 * t4 + k0 * 16;
                unsigned b0 = *reinterpret_cast<const unsigned*>(vp);
                unsigned b1 = *reinterpret_cast<const unsigned*>(vp + 8);
#pragma unroll
                for (int T = 0; T < 2; T++) {
                    asm volatile(
                        "mma.sync.aligned.m16n8k16.row.col.f32.bf16.bf16.f32 "
                        "{%0,%1,%2,%3}, {%4,%5,%6,%7}, {%8,%9}, {%0,%1,%2,%3};\n"
                        : "+f"(acc[T][nt][0]), "+f"(acc[T][nt][1]),
                          "+f"(acc[T][nt][2]), "+f"(acc[T][nt][3])
                        : "r"(afr[T][0]), "r"(afr[T][1]),
                          "r"(afr[T][2]), "r"(afr[T][3]),
                          "r"(b0), "r"(b1));
                }
            }
        }
        // exp-accumulate this 64-neg chunk (|logit| <= 10, fp32 safe, no max)
#pragma unroll
        for (int T = 0; T < 2; T++)
#pragma unroll
            for (int nt = 0; nt < 8; nt++) {
                rs[T][0] += __expf(acc[T][nt][0] * INV_T)
                          + __expf(acc[T][nt][1] * INV_T);
                rs[T][1] += __expf(acc[T][nt][2] * INV_T)
                          + __expf(acc[T][nt][3] * INV_T);
            }
    }

    // reduce exp-sums across the 4 lanes of each row group
#pragma unroll
    for (int T = 0; T < 2; T++) {
        rs[T][0] += __shfl_xor_sync(0xffffffffu, rs[T][0], 1);
        rs[T][0] += __shfl_xor_sync(0xffffffffu, rs[T][0], 2);
        rs[T][1] += __shfl_xor_sync(0xffffffffu, rs[T][1], 1);
        rs[T][1] += __shfl_xor_sync(0xffffffffu, rs[T][1], 2);
    }

    float contrib = 0.0f;
    if (t4 == 0) {
#pragma unroll
        for (int T = 0; T < 2; T++) {
            long long r0 = rowG + T * 16;
            if (r0 < n)
                contrib += sPos[warp * 32 + T * 16 + g]
                         - (logf(rs[T][0]) - LOG_S);
            if (r0 + 8 < n)
                contrib += sPos[warp * 32 + T * 16 + g + 8]
                         - (logf(rs[T][1]) - LOG_S);
        }
    }
#pragma unroll
    for (int o = 16; o > 0; o >>= 1)
        contrib += __shfl_xor_sync(0xffffffffu, contrib, o);
    if (lane == 0) sRed[warp] = contrib;
    __syncthreads();
    if (tid == 0) {
        float s = 0.0f;
#pragma unroll
        for (int w = 0; w < 8; w++) s += sRed[w];
        g_partial[blockIdx.x] = s;
    }
}

// ---------------------------------------------------------------------------
// Kernel 3: deterministic final reduction, loss = -sum / N
// ---------------------------------------------------------------------------
__global__ void finalize_kernel(float* __restrict__ out, int n, int nblocks) {
    __shared__ float sh[256];
    float s = 0.0f;
    for (int i = threadIdx.x; i < nblocks; i += 256) s += g_partial[i];
    sh[threadIdx.x] = s;
    __syncthreads();
    for (int o = 128; o > 0; o >>= 1) {
        if (threadIdx.x < o) sh[threadIdx.x] += sh[threadIdx.x + o];
        __syncthreads();
    }
    if (threadIdx.x == 0) out[0] = -sh[0] / (float)n;
}

// ---------------------------------------------------------------------------
extern "C" void kernel_launch(void* const* d_in, const int* in_sizes, int n_in,
                              void* d_out, int out_size) {
    const float* E   = (const float*)d_in[0];
    const void*  pos = d_in[1];
    const void*  neg = d_in[2];
    int n = in_sizes[1];   // number of edges

    // 0) detect index dtype (int32 vs int64)
    detect_idx_kernel<<<1, 128>>>(neg, n);

    // 1) normalize rows -> bf16
    int nblk_norm = (n + 7) / 8;   // 8 warps per 256-thread block, 1 row/warp
    normalize_kernel<<<nblk_norm, 256>>>(E, n);

    // 2) fused positive-dot + negative-GEMM + logsumexp
    int nblocks = (n + MTILE - 1) / MTILE;
    size_t smem = (size_t)(SNEG * STRIDE) * sizeof(__nv_bfloat16)
                + (size_t)(MTILE + 8) * sizeof(float);
    cudaFuncSetAttribute(main_kernel,
                         cudaFuncAttributeMaxDynamicSharedMemorySize, (int)smem);
    main_kernel<<<nblocks, 256, smem>>>(pos, neg, n);

    // 3) deterministic reduction into the scalar output
    finalize_kernel<<<1, 256>>>((float*)d_out, n, nblocks);
}